// round 2
// baseline (speedup 1.0000x reference)
#include <cuda_runtime.h>
#include <math.h>

#define NNODES 50000
#define NEDGES 800000
#define NGRAPH 128
#define DFEAT  128
#define DEMB   256
#define DCAT   1024   // 4 * DEMB
#define DTGT   18

// ---------------- scratch (device globals) -------------------------------------
__device__ float g_hc  [(size_t)NNODES * DCAT];   // concat of 4 layer outputs
__device__ float g_agg [(size_t)NNODES * DEMB];   // neighbor-max aggregate
__device__ float g_mid [(size_t)NNODES * DEMB];   // pre-activation temp
__device__ int   g_deg [NNODES];
__device__ int   g_rowptr[NNODES + 1];
__device__ int   g_cursor[NNODES];
__device__ int   g_col [NEDGES];
__device__ int   g_gstart[NGRAPH];
__device__ int   g_gcnt [NGRAPH];
__device__ float g_pool[NGRAPH * DCAT];
__device__ int   g_is64;

// ---------------- index dtype handling -----------------------------------------
__device__ __forceinline__ int load_idx(const void* p, long long i) {
    if (g_is64) return (int)((const long long*)p)[i];
    return ((const int*)p)[i];
}

__global__ void k_init(int n) {
    int i = blockIdx.x * blockDim.x + threadIdx.x;
    int stride = gridDim.x * blockDim.x;
    for (int j = i; j < n; j += stride) g_deg[j] = 0;
    if (i < NGRAPH) { g_gstart[i] = 0x7fffffff; g_gcnt[i] = 0; }
    if (i == 0) g_is64 = 1;
}

// Probe: interpret the edge buffer as int64. If it is really int32, adjacent
// index pairs combine into values >= 2^32 (or negative) almost surely -> flag 0.
__global__ void k_detect(const void* ei, long long ecnt, int nmax) {
    long long i = blockIdx.x * (long long)blockDim.x + threadIdx.x;
    long long stride = gridDim.x * (long long)blockDim.x;
    const long long* p = (const long long*)ei;
    for (long long j = i; j < ecnt; j += stride) {
        long long v = p[j];
        if (v < 0 || v >= nmax) g_is64 = 0;
    }
}

// ---------------- CSR build -----------------------------------------------------
__global__ void k_hist(const void* ei, long long E) {
    long long i = blockIdx.x * (long long)blockDim.x + threadIdx.x;
    long long stride = gridDim.x * (long long)blockDim.x;
    for (long long e = i; e < E; e += stride) {
        int dst = load_idx(ei, E + e);
        atomicAdd(&g_deg[dst], 1);
    }
}

__global__ void k_scan(int n) {
    __shared__ int sh[1024];
    __shared__ int scarry;
    int tid = threadIdx.x;
    if (tid == 0) { scarry = 0; g_rowptr[0] = 0; }
    __syncthreads();
    for (int base = 0; base < n; base += 1024) {
        int i = base + tid;
        int v = (i < n) ? g_deg[i] : 0;
        sh[tid] = v;
        __syncthreads();
        #pragma unroll
        for (int off = 1; off < 1024; off <<= 1) {
            int t = (tid >= off) ? sh[tid - off] : 0;
            __syncthreads();
            sh[tid] += t;
            __syncthreads();
        }
        int carry = scarry;
        int total = sh[1023];
        int incl = carry + sh[tid];
        if (i < n) {
            g_rowptr[i + 1] = incl;
            g_cursor[i]     = incl - v;   // exclusive prefix = row start
        }
        __syncthreads();
        if (tid == 0) scarry = carry + total;
        __syncthreads();
    }
}

__global__ void k_scatter(const void* ei, long long E) {
    long long i = blockIdx.x * (long long)blockDim.x + threadIdx.x;
    long long stride = gridDim.x * (long long)blockDim.x;
    for (long long e = i; e < E; e += stride) {
        int src = load_idx(ei, e);
        int dst = load_idx(ei, E + e);
        int pos = atomicAdd(&g_cursor[dst], 1);
        g_col[pos] = src;
    }
}

// ---------------- neighbor max aggregation -------------------------------------
// blockDim = (64, 4): 64 lanes * float4 = 256 feats; 4 nodes per block.
__global__ void k_segmax(const float* __restrict__ hprev, int ldh, int din, int n) {
    int node = blockIdx.x * blockDim.y + threadIdx.y;
    int tx = threadIdx.x;
    if (node >= n) return;
    if (tx * 4 >= din) return;
    int p0 = g_rowptr[node], p1 = g_rowptr[node + 1];
    float4 acc = make_float4(-INFINITY, -INFINITY, -INFINITY, -INFINITY);
    int p = p0;
    // 2-way unrolled for MLP
    for (; p + 1 < p1; p += 2) {
        int nb0 = g_col[p], nb1 = g_col[p + 1];
        float4 v0 = *(const float4*)&hprev[(size_t)nb0 * ldh + tx * 4];
        float4 v1 = *(const float4*)&hprev[(size_t)nb1 * ldh + tx * 4];
        acc.x = fmaxf(acc.x, fmaxf(v0.x, v1.x));
        acc.y = fmaxf(acc.y, fmaxf(v0.y, v1.y));
        acc.z = fmaxf(acc.z, fmaxf(v0.z, v1.z));
        acc.w = fmaxf(acc.w, fmaxf(v0.w, v1.w));
    }
    if (p < p1) {
        int nb = g_col[p];
        float4 v = *(const float4*)&hprev[(size_t)nb * ldh + tx * 4];
        acc.x = fmaxf(acc.x, v.x); acc.y = fmaxf(acc.y, v.y);
        acc.z = fmaxf(acc.z, v.z); acc.w = fmaxf(acc.w, v.w);
    }
    if (p0 == p1) acc = make_float4(0.f, 0.f, 0.f, 0.f);
    *(float4*)&g_agg[(size_t)node * DEMB + tx * 4] = acc;
}

// ---------------- fp32 tiled GEMM: C = A1@B1 + A2@B2 + bias (optional relu) ----
// A: [M,K] row-major (lda), B: [K,256] row-major, C: [M,ldc]. 128x128 C tile.
#define BM 128
#define BN 128
#define BK 16
#define ASTR 132

template <bool RELU>
__global__ __launch_bounds__(256, 2)
void k_gemm(const float* __restrict__ A1, int lda1, const float* __restrict__ B1, int K1,
            const float* __restrict__ A2, int lda2, const float* __restrict__ B2, int K2,
            const float* __restrict__ bias, float* __restrict__ C, int ldc, int M)
{
    __shared__ float As[BK * ASTR];
    __shared__ float Bs[BK * BN];
    int tid = threadIdx.x;
    int tx = tid & 15, ty = tid >> 4;
    int bm0 = blockIdx.x * BM;
    int bn0 = blockIdx.y * BN;
    int r0 = ty * 8, c0 = tx * 8;
    float acc[8][8];
    #pragma unroll
    for (int i = 0; i < 8; i++)
        #pragma unroll
        for (int j = 0; j < 8; j++) acc[i][j] = 0.f;

    #pragma unroll
    for (int phase = 0; phase < 2; ++phase) {
        const float* A = phase ? A2 : A1;
        const float* B = phase ? B2 : B1;
        int K   = phase ? K2   : K1;
        int lda = phase ? lda2 : lda1;
        if (A == nullptr) break;
        for (int k0 = 0; k0 < K; k0 += BK) {
            #pragma unroll
            for (int i = 0; i < 2; i++) {
                int idx = tid + i * 256;          // 512 float4 for A tile
                int row = idx >> 2, cq = idx & 3;
                int grow = bm0 + row;
                float4 a = make_float4(0.f, 0.f, 0.f, 0.f);
                if (grow < M) a = *(const float4*)&A[(size_t)grow * lda + k0 + cq * 4];
                As[(cq * 4 + 0) * ASTR + row] = a.x;
                As[(cq * 4 + 1) * ASTR + row] = a.y;
                As[(cq * 4 + 2) * ASTR + row] = a.z;
                As[(cq * 4 + 3) * ASTR + row] = a.w;
            }
            #pragma unroll
            for (int i = 0; i < 2; i++) {
                int idx = tid + i * 256;          // 512 float4 for B tile
                int kr = idx >> 5, cq = idx & 31;
                *(float4*)&Bs[kr * BN + cq * 4] =
                    *(const float4*)&B[(size_t)(k0 + kr) * DEMB + bn0 + cq * 4];
            }
            __syncthreads();
            #pragma unroll
            for (int k = 0; k < BK; k++) {
                float4 a0 = *(float4*)&As[k * ASTR + r0];
                float4 a1 = *(float4*)&As[k * ASTR + r0 + 4];
                float4 b0 = *(float4*)&Bs[k * BN + c0];
                float4 b1 = *(float4*)&Bs[k * BN + c0 + 4];
                float av[8] = {a0.x, a0.y, a0.z, a0.w, a1.x, a1.y, a1.z, a1.w};
                float bv[8] = {b0.x, b0.y, b0.z, b0.w, b1.x, b1.y, b1.z, b1.w};
                #pragma unroll
                for (int i = 0; i < 8; i++)
                    #pragma unroll
                    for (int j = 0; j < 8; j++)
                        acc[i][j] = fmaf(av[i], bv[j], acc[i][j]);
            }
            __syncthreads();
        }
    }

    #pragma unroll
    for (int i = 0; i < 8; i++) {
        int grow = bm0 + r0 + i;
        if (grow >= M) continue;
        #pragma unroll
        for (int j = 0; j < 8; j += 4) {
            float4 v;
            v.x = acc[i][j + 0] + bias[bn0 + c0 + j + 0];
            v.y = acc[i][j + 1] + bias[bn0 + c0 + j + 1];
            v.z = acc[i][j + 2] + bias[bn0 + c0 + j + 2];
            v.w = acc[i][j + 3] + bias[bn0 + c0 + j + 3];
            if (RELU) {
                v.x = fmaxf(v.x, 0.f); v.y = fmaxf(v.y, 0.f);
                v.z = fmaxf(v.z, 0.f); v.w = fmaxf(v.w, 0.f);
            }
            *(float4*)&C[(size_t)grow * ldc + bn0 + c0 + j] = v;
        }
    }
}

// ---------------- graph pooling -------------------------------------------------
__global__ void k_gbounds(const void* batch, int n) {
    int i = blockIdx.x * blockDim.x + threadIdx.x;
    int stride = gridDim.x * blockDim.x;
    for (int j = i; j < n; j += stride) {
        int b = load_idx(batch, j);
        atomicMin(&g_gstart[b], j);
        atomicAdd(&g_gcnt[b], 1);
    }
}

__global__ void k_pool() {
    int g = blockIdx.x;
    int c = threadIdx.x * 4;            // 256 threads cover 1024 cols
    int s = g_gstart[g], cnt = g_gcnt[g];
    float4 acc = make_float4(-INFINITY, -INFINITY, -INFINITY, -INFINITY);
    for (int r = 0; r < cnt; ++r) {
        float4 v = *(const float4*)&g_hc[(size_t)(s + r) * DCAT + c];
        acc.x = fmaxf(acc.x, v.x); acc.y = fmaxf(acc.y, v.y);
        acc.z = fmaxf(acc.z, v.z); acc.w = fmaxf(acc.w, v.w);
    }
    if (cnt == 0) acc = make_float4(0.f, 0.f, 0.f, 0.f);
    *(float4*)&g_pool[g * DCAT + c] = acc;
}

// ---------------- readout: fc1 -> relu -> fc2 -> log_softmax --------------------
__global__ void k_readout(const float* __restrict__ fc1W, const float* __restrict__ fc1b,
                          const float* __restrict__ fc2W, const float* __restrict__ fc2b,
                          float* __restrict__ out, int out_size)
{
    int g = blockIdx.x;
    int c = threadIdx.x;                // 256 threads
    __shared__ float sg[DCAT];
    __shared__ float sll[DEMB];
    __shared__ float slog[DTGT];
    for (int k = c; k < DCAT; k += 256) sg[k] = g_pool[g * DCAT + k];
    __syncthreads();
    float a = fc1b[c];
    #pragma unroll 4
    for (int k = 0; k < DCAT; k++) a = fmaf(sg[k], fc1W[k * DEMB + c], a);
    float ll = fmaxf(a, 0.f);
    sll[c] = ll;
    __syncthreads();
    if (c < DTGT) {
        float o = fc2b[c];
        #pragma unroll 4
        for (int k = 0; k < DEMB; k++) o = fmaf(sll[k], fc2W[k * DTGT + c], o);
        slog[c] = o;
    }
    __syncthreads();
    if (c < DTGT) {
        float m = -INFINITY;
        for (int k = 0; k < DTGT; k++) m = fmaxf(m, slog[k]);
        float se = 0.f;
        for (int k = 0; k < DTGT; k++) se += expf(slog[k] - m);
        float lse = m + logf(se);
        out[g * DTGT + c] = slog[c] - lse;
        if (out_size >= 2 * NGRAPH * DTGT)
            out[NGRAPH * DTGT + g * DTGT + c] = slog[c];
    }
    if (out_size >= 2 * NGRAPH * DTGT + NGRAPH * DEMB)
        out[2 * NGRAPH * DTGT + g * DEMB + c] = ll;
}

__global__ void k_zero(float* p, int n) {
    int i = blockIdx.x * blockDim.x + threadIdx.x;
    int stride = gridDim.x * blockDim.x;
    for (int j = i; j < n; j += stride) p[j] = 0.f;
}

// ---------------- launch --------------------------------------------------------
extern "C" void kernel_launch(void* const* d_in, const int* in_sizes, int n_in,
                              void* d_out, int out_size)
{
    const float* x     = (const float*)d_in[0];
    const void*  ei    = d_in[1];
    const void*  batch = d_in[2];
    const float* W[4][5];
    for (int l = 0; l < 4; l++)
        for (int k = 0; k < 5; k++)
            W[l][k] = (const float*)d_in[3 + 5 * l + k];   // Wl, bl, Wr, Wm, bm
    const float* fc1W = (const float*)d_in[23];
    const float* fc1b = (const float*)d_in[24];
    const float* fc2W = (const float*)d_in[25];
    const float* fc2b = (const float*)d_in[26];
    float* out = (float*)d_out;

    // Resolve scratch-buffer device addresses (host API, not a stream op;
    // legal during graph capture, and not an allocation).
    float* hc_base  = nullptr;
    float* agg_base = nullptr;
    float* mid_base = nullptr;
    cudaGetSymbolAddress((void**)&hc_base,  g_hc);
    cudaGetSymbolAddress((void**)&agg_base, g_agg);
    cudaGetSymbolAddress((void**)&mid_base, g_mid);

    int Nn = in_sizes[0] / DFEAT;
    long long E = in_sizes[1] / 2;
    if (Nn > NNODES) Nn = NNODES;
    if (E > NEDGES) E = NEDGES;

    int tb = 256;
    int gbN = (Nn + tb - 1) / tb;
    int gbE = (int)((E + tb - 1) / tb); if (gbE > 2048) gbE = 2048;

    k_init<<<gbN, tb>>>(Nn);
    k_detect<<<512, tb>>>(ei, E, Nn);
    k_hist<<<gbE, tb>>>(ei, E);
    k_scan<<<1, 1024>>>(Nn);
    k_scatter<<<gbE, tb>>>(ei, E);
    k_zero<<<(out_size + tb - 1) / tb, tb>>>(out, out_size);

    dim3 segBlk(64, 4);
    int segGrid = (Nn + 3) / 4;
    dim3 gemmGrid((Nn + BM - 1) / BM, DEMB / BN);

    for (int l = 0; l < 4; l++) {
        const float* hp;
        int ldh, din;
        if (l == 0) { hp = x;                                   ldh = DFEAT; din = DFEAT; }
        else        { hp = hc_base + (size_t)(l - 1) * DEMB;    ldh = DCAT;  din = DEMB;  }

        k_segmax<<<segGrid, segBlk>>>(hp, ldh, din, Nn);
        // mid = agg @ Wl + hp @ Wr + bl
        k_gemm<false><<<gemmGrid, 256>>>(agg_base, DEMB, W[l][0], din,
                                         hp, ldh, W[l][2], din,
                                         W[l][1], mid_base, DEMB, Nn);
        // hc[:, l*256:(l+1)*256] = relu(mid @ Wm + bm)
        k_gemm<true><<<gemmGrid, 256>>>(mid_base, DEMB, W[l][3], DEMB,
                                        nullptr, 0, nullptr, 0,
                                        W[l][4], hc_base + (size_t)l * DEMB, DCAT, Nn);
    }

    k_gbounds<<<gbN, tb>>>(batch, Nn);
    k_pool<<<NGRAPH, 256>>>();
    k_readout<<<NGRAPH, 256>>>(fc1W, fc1b, fc2W, fc2b, out, out_size);
}

// round 4
// speedup vs baseline: 1.7953x; 1.7953x over previous
#include <cuda_runtime.h>
#include <math.h>

#define NNODES 50000
#define NEDGES 800000
#define NGRAPH 128
#define DFEAT  128
#define DEMB   256
#define DCAT   1024   // 4 * DEMB
#define DTGT   18

// ---------------- scratch (device globals) -------------------------------------
__device__ float g_hc  [(size_t)NNODES * DCAT];   // concat of 4 layer outputs
__device__ float g_agg [(size_t)NNODES * DEMB];   // neighbor-max aggregate
__device__ float g_mid [(size_t)NNODES * DEMB];   // pre-activation temp
__device__ int   g_deg [NNODES];
__device__ int   g_rowptr[NNODES + 1];
__device__ int   g_cursor[NNODES];
__device__ int   g_col [NEDGES];
__device__ int   g_gstart[NGRAPH];
__device__ int   g_gcnt [NGRAPH];
__device__ float g_pool[NGRAPH * DCAT];
__device__ int   g_is64;
__device__ int   g_bsum[128];

// ---------------- index dtype handling -----------------------------------------
__device__ __forceinline__ int load_idx(const void* p, long long i) {
    if (g_is64) return (int)((const long long*)p)[i];
    return ((const int*)p)[i];
}

__global__ void k_init(int n) {
    int i = blockIdx.x * blockDim.x + threadIdx.x;
    int stride = gridDim.x * blockDim.x;
    for (int j = i; j < n; j += stride) g_deg[j] = 0;
    if (i < NGRAPH) { g_gstart[i] = 0x7fffffff; g_gcnt[i] = 0; }
    if (i == 0) g_is64 = 1;
}

// Probe: interpret the edge buffer as int64. If it is really int32, adjacent
// index pairs combine into values >= 2^32 (or negative) almost surely -> flag 0.
__global__ void k_detect(const void* ei, long long ecnt, int nmax) {
    long long i = blockIdx.x * (long long)blockDim.x + threadIdx.x;
    long long stride = gridDim.x * (long long)blockDim.x;
    const long long* p = (const long long*)ei;
    for (long long j = i; j < ecnt; j += stride) {
        long long v = p[j];
        if (v < 0 || v >= nmax) g_is64 = 0;
    }
}

// ---------------- CSR build -----------------------------------------------------
__global__ void k_hist(const void* ei, long long E) {
    long long i = blockIdx.x * (long long)blockDim.x + threadIdx.x;
    long long stride = gridDim.x * (long long)blockDim.x;
    for (long long e = i; e < E; e += stride) {
        int dst = load_idx(ei, E + e);
        atomicAdd(&g_deg[dst], 1);
    }
}

// Hierarchical scan: phase 1 — per-block inclusive scan (1024 elems/block)
__global__ void k_scan1(int n) {
    __shared__ int sh[1024];
    int tid = threadIdx.x;
    int i = blockIdx.x * 1024 + tid;
    int v = (i < n) ? g_deg[i] : 0;
    sh[tid] = v;
    __syncthreads();
    #pragma unroll
    for (int off = 1; off < 1024; off <<= 1) {
        int t = (tid >= off) ? sh[tid - off] : 0;
        __syncthreads();
        sh[tid] += t;
        __syncthreads();
    }
    if (i < n) {
        g_rowptr[i + 1] = sh[tid];       // block-local inclusive (offset added later)
        g_cursor[i]     = sh[tid] - v;   // block-local exclusive
    }
    if (tid == 1023) g_bsum[blockIdx.x] = sh[1023];
    if (i == 0) g_rowptr[0] = 0;
}

// phase 2 — serial scan of <=128 block sums -> exclusive offsets
__global__ void k_scan2(int nblk) {
    if (threadIdx.x == 0) {
        int run = 0;
        for (int b = 0; b < nblk; b++) { int t = g_bsum[b]; g_bsum[b] = run; run += t; }
    }
}

// phase 3 — add block offsets
__global__ void k_scan3(int n) {
    int tid = threadIdx.x;
    int i = blockIdx.x * 1024 + tid;
    if (i < n) {
        int off = g_bsum[blockIdx.x];
        g_rowptr[i + 1] += off;
        g_cursor[i]     += off;
    }
}

__global__ void k_scatter(const void* ei, long long E) {
    long long i = blockIdx.x * (long long)blockDim.x + threadIdx.x;
    long long stride = gridDim.x * (long long)blockDim.x;
    for (long long e = i; e < E; e += stride) {
        int src = load_idx(ei, e);
        int dst = load_idx(ei, E + e);
        int pos = atomicAdd(&g_cursor[dst], 1);
        g_col[pos] = src;
    }
}

// ---------------- neighbor max aggregation -------------------------------------
// blockDim = (64, 4): 64 lanes * float4 = 256 feats; 4 nodes per block.
__global__ void k_segmax(const float* __restrict__ hprev, int ldh, int din, int n) {
    int node = blockIdx.x * blockDim.y + threadIdx.y;
    int tx = threadIdx.x;
    if (node >= n) return;
    if (tx * 4 >= din) return;
    int p0 = g_rowptr[node], p1 = g_rowptr[node + 1];
    float4 acc = make_float4(-INFINITY, -INFINITY, -INFINITY, -INFINITY);
    int p = p0;
    for (; p + 1 < p1; p += 2) {
        int nb0 = g_col[p], nb1 = g_col[p + 1];
        float4 v0 = *(const float4*)&hprev[(size_t)nb0 * ldh + tx * 4];
        float4 v1 = *(const float4*)&hprev[(size_t)nb1 * ldh + tx * 4];
        acc.x = fmaxf(acc.x, fmaxf(v0.x, v1.x));
        acc.y = fmaxf(acc.y, fmaxf(v0.y, v1.y));
        acc.z = fmaxf(acc.z, fmaxf(v0.z, v1.z));
        acc.w = fmaxf(acc.w, fmaxf(v0.w, v1.w));
    }
    if (p < p1) {
        int nb = g_col[p];
        float4 v = *(const float4*)&hprev[(size_t)nb * ldh + tx * 4];
        acc.x = fmaxf(acc.x, v.x); acc.y = fmaxf(acc.y, v.y);
        acc.z = fmaxf(acc.z, v.z); acc.w = fmaxf(acc.w, v.w);
    }
    if (p0 == p1) acc = make_float4(0.f, 0.f, 0.f, 0.f);
    *(float4*)&g_agg[(size_t)node * DEMB + tx * 4] = acc;
}

// ---------------- tf32 tensor-core GEMM ----------------------------------------
// C[M,ldc] = A1@B1 + A2@B2 + bias (optional relu). A row-major, B [K,256] row-major.
// Tile: 128x128x32. 4 warps (2x2), warp tile 64x64 of m16n8k8 mma.sync tf32.
#define BM 128
#define BN 128
#define BK 32
#define SSTR 132   // smem row stride (floats): conflict-free frag reads

__device__ __forceinline__ float to_tf32(float f) {
    unsigned u;
    asm("cvt.rna.tf32.f32 %0, %1;" : "=r"(u) : "f"(f));
    return __uint_as_float(u);
}

__device__ __forceinline__ void mma_tf32(float c[4], unsigned a0, unsigned a1,
                                         unsigned a2, unsigned a3,
                                         unsigned b0, unsigned b1) {
    asm volatile(
        "mma.sync.aligned.m16n8k8.row.col.f32.tf32.tf32.f32 "
        "{%0,%1,%2,%3}, {%4,%5,%6,%7}, {%8,%9}, {%0,%1,%2,%3};\n"
        : "+f"(c[0]), "+f"(c[1]), "+f"(c[2]), "+f"(c[3])
        : "r"(a0), "r"(a1), "r"(a2), "r"(a3), "r"(b0), "r"(b1));
}

template <bool RELU>
__global__ __launch_bounds__(128, 2)
void k_gemm_tc(const float* __restrict__ A1, int lda1, const float* __restrict__ B1, int K1,
               const float* __restrict__ A2, int lda2, const float* __restrict__ B2, int K2,
               const float* __restrict__ bias, float* __restrict__ C, int ldc, int M)
{
    __shared__ float As[BK * SSTR];
    __shared__ float Bs[BK * SSTR];
    int tid  = threadIdx.x;
    int warp = tid >> 5, lane = tid & 31;
    int wm = warp & 1, wn = warp >> 1;          // 2x2 warp grid
    int m_base = wm * 64, n_base = wn * 64;
    int g = lane >> 2, t4 = lane & 3;
    int bm0 = blockIdx.x * BM;
    int bn0 = blockIdx.y * BN;

    float c[4][8][4];
    #pragma unroll
    for (int i = 0; i < 4; i++)
        #pragma unroll
        for (int j = 0; j < 8; j++)
            #pragma unroll
            for (int q = 0; q < 4; q++) c[i][j][q] = 0.f;

    for (int phase = 0; phase < 2; ++phase) {
        const float* A = phase ? A2 : A1;
        const float* B = phase ? B2 : B1;
        int K   = phase ? K2   : K1;
        int lda = phase ? lda2 : lda1;
        if (A == nullptr) break;

        for (int k0 = 0; k0 < K; k0 += BK) {
            // A tile: 128 rows x 32 k, transposed into As[k][m]
            #pragma unroll
            for (int t = 0; t < 8; t++) {
                int idx = tid + t * 128;          // 1024 float4
                int row = idx >> 3, c4 = idx & 7;
                float4 a = make_float4(0.f, 0.f, 0.f, 0.f);
                if (bm0 + row < M)
                    a = *(const float4*)&A[(size_t)(bm0 + row) * lda + k0 + c4 * 4];
                As[(c4 * 4 + 0) * SSTR + row] = to_tf32(a.x);
                As[(c4 * 4 + 1) * SSTR + row] = to_tf32(a.y);
                As[(c4 * 4 + 2) * SSTR + row] = to_tf32(a.z);
                As[(c4 * 4 + 3) * SSTR + row] = to_tf32(a.w);
            }
            // B tile: 32 k x 128 n into Bs[k][n]
            #pragma unroll
            for (int t = 0; t < 8; t++) {
                int idx = tid + t * 128;
                int kr = idx >> 5, cq = idx & 31;
                float4 b = *(const float4*)&B[(size_t)(k0 + kr) * DEMB + bn0 + cq * 4];
                float4 bb;
                bb.x = to_tf32(b.x); bb.y = to_tf32(b.y);
                bb.z = to_tf32(b.z); bb.w = to_tf32(b.w);
                *(float4*)&Bs[kr * SSTR + cq * 4] = bb;
            }
            __syncthreads();

            #pragma unroll
            for (int ks = 0; ks < 4; ks++) {
                int kk = ks * 8;
                unsigned af[4][4], bf[8][2];
                #pragma unroll
                for (int i = 0; i < 4; i++) {
                    int r = m_base + i * 16 + g;
                    af[i][0] = __float_as_uint(As[(kk + t4) * SSTR + r]);
                    af[i][1] = __float_as_uint(As[(kk + t4) * SSTR + r + 8]);
                    af[i][2] = __float_as_uint(As[(kk + t4 + 4) * SSTR + r]);
                    af[i][3] = __float_as_uint(As[(kk + t4 + 4) * SSTR + r + 8]);
                }
                #pragma unroll
                for (int j = 0; j < 8; j++) {
                    int nn = n_base + j * 8 + g;
                    bf[j][0] = __float_as_uint(Bs[(kk + t4) * SSTR + nn]);
                    bf[j][1] = __float_as_uint(Bs[(kk + t4 + 4) * SSTR + nn]);
                }
                #pragma unroll
                for (int i = 0; i < 4; i++)
                    #pragma unroll
                    for (int j = 0; j < 8; j++)
                        mma_tf32(c[i][j], af[i][0], af[i][1], af[i][2], af[i][3],
                                 bf[j][0], bf[j][1]);
            }
            __syncthreads();
        }
    }

    // epilogue
    #pragma unroll
    for (int i = 0; i < 4; i++) {
        int row0 = bm0 + m_base + i * 16 + g;
        #pragma unroll
        for (int j = 0; j < 8; j++) {
            int col = bn0 + n_base + j * 8 + 2 * t4;
            float bx = bias[col], by = bias[col + 1];
            float v0 = c[i][j][0] + bx, v1 = c[i][j][1] + by;
            float v2 = c[i][j][2] + bx, v3 = c[i][j][3] + by;
            if (RELU) {
                v0 = fmaxf(v0, 0.f); v1 = fmaxf(v1, 0.f);
                v2 = fmaxf(v2, 0.f); v3 = fmaxf(v3, 0.f);
            }
            if (row0 < M)     *(float2*)&C[(size_t)row0 * ldc + col]       = make_float2(v0, v1);
            if (row0 + 8 < M) *(float2*)&C[(size_t)(row0 + 8) * ldc + col] = make_float2(v2, v3);
        }
    }
}

// ---------------- graph pooling -------------------------------------------------
__global__ void k_gbounds(const void* batch, int n) {
    int i = blockIdx.x * blockDim.x + threadIdx.x;
    int stride = gridDim.x * blockDim.x;
    for (int j = i; j < n; j += stride) {
        int b = load_idx(batch, j);
        atomicMin(&g_gstart[b], j);
        atomicAdd(&g_gcnt[b], 1);
    }
}

__global__ void k_pool() {
    int g = blockIdx.x;
    int c = threadIdx.x * 4;            // 256 threads cover 1024 cols
    int s = g_gstart[g], cnt = g_gcnt[g];
    float4 acc = make_float4(-INFINITY, -INFINITY, -INFINITY, -INFINITY);
    for (int r = 0; r < cnt; ++r) {
        float4 v = *(const float4*)&g_hc[(size_t)(s + r) * DCAT + c];
        acc.x = fmaxf(acc.x, v.x); acc.y = fmaxf(acc.y, v.y);
        acc.z = fmaxf(acc.z, v.z); acc.w = fmaxf(acc.w, v.w);
    }
    if (cnt == 0) acc = make_float4(0.f, 0.f, 0.f, 0.f);
    *(float4*)&g_pool[g * DCAT + c] = acc;
}

// ---------------- readout: fc1 -> relu -> fc2 -> log_softmax --------------------
__global__ void k_readout(const float* __restrict__ fc1W, const float* __restrict__ fc1b,
                          const float* __restrict__ fc2W, const float* __restrict__ fc2b,
                          float* __restrict__ out, int out_size)
{
    int g = blockIdx.x;
    int c = threadIdx.x;                // 256 threads
    __shared__ float sg[DCAT];
    __shared__ float sll[DEMB];
    __shared__ float slog[DTGT];
    for (int k = c; k < DCAT; k += 256) sg[k] = g_pool[g * DCAT + k];
    __syncthreads();
    float a = fc1b[c];
    #pragma unroll 4
    for (int k = 0; k < DCAT; k++) a = fmaf(sg[k], fc1W[k * DEMB + c], a);
    float ll = fmaxf(a, 0.f);
    sll[c] = ll;
    __syncthreads();
    if (c < DTGT) {
        float o = fc2b[c];
        #pragma unroll 4
        for (int k = 0; k < DEMB; k++) o = fmaf(sll[k], fc2W[k * DTGT + c], o);
        slog[c] = o;
    }
    __syncthreads();
    if (c < DTGT) {
        float m = -INFINITY;
        for (int k = 0; k < DTGT; k++) m = fmaxf(m, slog[k]);
        float se = 0.f;
        for (int k = 0; k < DTGT; k++) se += expf(slog[k] - m);
        float lse = m + logf(se);
        out[g * DTGT + c] = slog[c] - lse;
        if (out_size >= 2 * NGRAPH * DTGT)
            out[NGRAPH * DTGT + g * DTGT + c] = slog[c];
    }
    if (out_size >= 2 * NGRAPH * DTGT + NGRAPH * DEMB)
        out[2 * NGRAPH * DTGT + g * DEMB + c] = ll;
}

__global__ void k_zero(float* p, int n) {
    int i = blockIdx.x * blockDim.x + threadIdx.x;
    int stride = gridDim.x * blockDim.x;
    for (int j = i; j < n; j += stride) p[j] = 0.f;
}

// ---------------- launch --------------------------------------------------------
extern "C" void kernel_launch(void* const* d_in, const int* in_sizes, int n_in,
                              void* d_out, int out_size)
{
    const float* x     = (const float*)d_in[0];
    const void*  ei    = d_in[1];
    const void*  batch = d_in[2];
    const float* W[4][5];
    for (int l = 0; l < 4; l++)
        for (int k = 0; k < 5; k++)
            W[l][k] = (const float*)d_in[3 + 5 * l + k];   // Wl, bl, Wr, Wm, bm
    const float* fc1W = (const float*)d_in[23];
    const float* fc1b = (const float*)d_in[24];
    const float* fc2W = (const float*)d_in[25];
    const float* fc2b = (const float*)d_in[26];
    float* out = (float*)d_out;

    float* hc_base  = nullptr;
    float* agg_base = nullptr;
    float* mid_base = nullptr;
    cudaGetSymbolAddress((void**)&hc_base,  g_hc);
    cudaGetSymbolAddress((void**)&agg_base, g_agg);
    cudaGetSymbolAddress((void**)&mid_base, g_mid);

    int Nn = in_sizes[0] / DFEAT;
    long long E = in_sizes[1] / 2;
    if (Nn > NNODES) Nn = NNODES;
    if (E > NEDGES) E = NEDGES;

    int tb = 256;
    int gbN = (Nn + tb - 1) / tb;
    int gbE = (int)((E + tb - 1) / tb); if (gbE > 2048) gbE = 2048;
    int nScanBlk = (Nn + 1023) / 1024;

    k_init<<<gbN, tb>>>(Nn);
    k_detect<<<512, tb>>>(ei, E, Nn);
    k_hist<<<gbE, tb>>>(ei, E);
    k_scan1<<<nScanBlk, 1024>>>(Nn);
    k_scan2<<<1, 32>>>(nScanBlk);
    k_scan3<<<nScanBlk, 1024>>>(Nn);
    k_scatter<<<gbE, tb>>>(ei, E);
    k_zero<<<(out_size + tb - 1) / tb, tb>>>(out, out_size);

    dim3 segBlk(64, 4);
    int segGrid = (Nn + 3) / 4;
    dim3 gemmGrid((Nn + BM - 1) / BM, DEMB / BN);

    for (int l = 0; l < 4; l++) {
        const float* hp;
        int ldh, din;
        if (l == 0) { hp = x;                                ldh = DFEAT; din = DFEAT; }
        else        { hp = hc_base + (size_t)(l - 1) * DEMB; ldh = DCAT;  din = DEMB;  }

        k_segmax<<<segGrid, segBlk>>>(hp, ldh, din, Nn);
        // mid = agg @ Wl + hp @ Wr + bl
        k_gemm_tc<false><<<gemmGrid, 128>>>(agg_base, DEMB, W[l][0], din,
                                            hp, ldh, W[l][2], din,
                                            W[l][1], mid_base, DEMB, Nn);
        // hc[:, l*256:(l+1)*256] = relu(mid @ Wm + bm)
        k_gemm_tc<true><<<gemmGrid, 128>>>(mid_base, DEMB, W[l][3], DEMB,
                                           nullptr, 0, nullptr, 0,
                                           W[l][4], hc_base + (size_t)l * DEMB, DCAT, Nn);
    }

    k_gbounds<<<gbN, tb>>>(batch, Nn);
    k_pool<<<NGRAPH, 256>>>();
    k_readout<<<NGRAPH, 256>>>(fc1W, fc1b, fc2W, fc2b, out, out_size);
}

// round 6
// speedup vs baseline: 2.0800x; 1.1586x over previous
#include <cuda_runtime.h>
#include <math.h>

#define NNODES 50000
#define NEDGES 800000
#define NGRAPH 128
#define DFEAT  128
#define DEMB   256
#define DCAT   1024   // 4 * DEMB
#define DTGT   18
#define NWEIGHT 720896   // total tf32 weight floats (Wl/Wr/Wm x 4 layers)

// ---------------- scratch (device globals) -------------------------------------
__device__ float g_hc  [(size_t)NNODES * DCAT];   // concat of 4 layer outputs (tf32-rounded)
__device__ float g_agg [(size_t)NNODES * DEMB];   // neighbor-max aggregate (tf32 values)
__device__ float g_mid [(size_t)NNODES * DEMB];   // pre-activation temp (tf32-rounded)
__device__ float g_xtf [(size_t)NNODES * DFEAT];  // tf32-rounded copy of x
__device__ float g_wtf [NWEIGHT];                 // tf32-rounded weights
__device__ int   g_deg [NNODES];
__device__ int   g_rowptr[NNODES + 1];
__device__ int   g_cursor[NNODES];
__device__ int   g_col [NEDGES];
__device__ int   g_gstart[NGRAPH];
__device__ int   g_gcnt [NGRAPH];
__device__ float g_pool[NGRAPH * DCAT];
__device__ int   g_is64;
__device__ int   g_bsum[128];

// ---------------- helpers -------------------------------------------------------
__device__ __forceinline__ int load_idx(const void* p, long long i) {
    if (g_is64) return (int)((const long long*)p)[i];
    return ((const int*)p)[i];
}

__device__ __forceinline__ float to_tf32(float f) {
    unsigned u;
    asm("cvt.rna.tf32.f32 %0, %1;" : "=r"(u) : "f"(f));
    return __uint_as_float(u);
}

__device__ __forceinline__ void mma_tf32(float c[4], unsigned a0, unsigned a1,
                                         unsigned a2, unsigned a3,
                                         unsigned b0, unsigned b1) {
    asm volatile(
        "mma.sync.aligned.m16n8k8.row.col.f32.tf32.tf32.f32 "
        "{%0,%1,%2,%3}, {%4,%5,%6,%7}, {%8,%9}, {%0,%1,%2,%3};\n"
        : "+f"(c[0]), "+f"(c[1]), "+f"(c[2]), "+f"(c[3])
        : "r"(a0), "r"(a1), "r"(a2), "r"(a3), "r"(b0), "r"(b1));
}

__device__ __forceinline__ unsigned smem_u32(const void* p) {
    return (unsigned)__cvta_generic_to_shared(p);
}
__device__ __forceinline__ void cp_async16(unsigned dst, const void* src, int sz) {
    asm volatile("cp.async.cg.shared.global [%0], [%1], 16, %2;\n"
                 :: "r"(dst), "l"(src), "r"(sz));
}

// ---------------- setup / probe --------------------------------------------------
__global__ void k_init(int n) {
    int i = blockIdx.x * blockDim.x + threadIdx.x;
    int stride = gridDim.x * blockDim.x;
    for (int j = i; j < n; j += stride) g_deg[j] = 0;
    if (i < NGRAPH) { g_gstart[i] = 0x7fffffff; g_gcnt[i] = 0; }
    if (i == 0) g_is64 = 1;
}

__global__ void k_detect(const void* ei, long long ecnt, int nmax) {
    long long i = blockIdx.x * (long long)blockDim.x + threadIdx.x;
    long long stride = gridDim.x * (long long)blockDim.x;
    const long long* p = (const long long*)ei;
    for (long long j = i; j < ecnt; j += stride) {
        long long v = p[j];
        if (v < 0 || v >= nmax) g_is64 = 0;
    }
}

// one-shot tf32 rounding of x
__global__ void k_cvtX(const float* __restrict__ x, int n) {
    int i = blockIdx.x * blockDim.x + threadIdx.x;
    int stride = gridDim.x * blockDim.x;
    for (int j = i; j < n; j += stride) g_xtf[j] = to_tf32(x[j]);
}

// one-shot tf32 rounding of the 12 weight matrices
struct WSeg { const float* p; int off; int len; };
struct WArgs { WSeg s[12]; };
__global__ void k_cvtW(WArgs a) {
    int base = blockIdx.x * blockDim.x + threadIdx.x;
    int stride = gridDim.x * blockDim.x;
    for (int sgi = 0; sgi < 12; sgi++) {
        const float* p = a.s[sgi].p;
        int off = a.s[sgi].off, len = a.s[sgi].len;
        for (int i = base; i < len; i += stride) g_wtf[off + i] = to_tf32(p[i]);
    }
}

// ---------------- CSR build -----------------------------------------------------
__global__ void k_hist(const void* ei, long long E) {
    long long i = blockIdx.x * (long long)blockDim.x + threadIdx.x;
    long long stride = gridDim.x * (long long)blockDim.x;
    for (long long e = i; e < E; e += stride) {
        int dst = load_idx(ei, E + e);
        atomicAdd(&g_deg[dst], 1);
    }
}

__global__ void k_scan1(int n) {
    __shared__ int sh[1024];
    int tid = threadIdx.x;
    int i = blockIdx.x * 1024 + tid;
    int v = (i < n) ? g_deg[i] : 0;
    sh[tid] = v;
    __syncthreads();
    #pragma unroll
    for (int off = 1; off < 1024; off <<= 1) {
        int t = (tid >= off) ? sh[tid - off] : 0;
        __syncthreads();
        sh[tid] += t;
        __syncthreads();
    }
    if (i < n) {
        g_rowptr[i + 1] = sh[tid];
        g_cursor[i]     = sh[tid] - v;
    }
    if (tid == 1023) g_bsum[blockIdx.x] = sh[1023];
    if (i == 0) g_rowptr[0] = 0;
}

__global__ void k_scan2(int nblk) {
    if (threadIdx.x == 0) {
        int run = 0;
        for (int b = 0; b < nblk; b++) { int t = g_bsum[b]; g_bsum[b] = run; run += t; }
    }
}

__global__ void k_scan3(int n) {
    int tid = threadIdx.x;
    int i = blockIdx.x * 1024 + tid;
    if (i < n) {
        int off = g_bsum[blockIdx.x];
        g_rowptr[i + 1] += off;
        g_cursor[i]     += off;
    }
}

__global__ void k_scatter(const void* ei, long long E) {
    long long i = blockIdx.x * (long long)blockDim.x + threadIdx.x;
    long long stride = gridDim.x * (long long)blockDim.x;
    for (long long e = i; e < E; e += stride) {
        int src = load_idx(ei, e);
        int dst = load_idx(ei, E + e);
        int pos = atomicAdd(&g_cursor[dst], 1);
        g_col[pos] = src;
    }
}

// ---------------- neighbor max aggregation -------------------------------------
// blockDim = (64, 4). Inputs are already tf32-rounded; max preserves tf32.
__global__ void k_segmax(const float* __restrict__ hprev, int ldh, int din, int n) {
    int node = blockIdx.x * blockDim.y + threadIdx.y;
    int tx = threadIdx.x;
    if (node >= n) return;
    if (tx * 4 >= din) return;
    int p0 = g_rowptr[node], p1 = g_rowptr[node + 1];
    float4 acc = make_float4(-INFINITY, -INFINITY, -INFINITY, -INFINITY);
    int p = p0;
    for (; p + 3 < p1; p += 4) {
        int nb0 = g_col[p], nb1 = g_col[p + 1], nb2 = g_col[p + 2], nb3 = g_col[p + 3];
        float4 v0 = *(const float4*)&hprev[(size_t)nb0 * ldh + tx * 4];
        float4 v1 = *(const float4*)&hprev[(size_t)nb1 * ldh + tx * 4];
        float4 v2 = *(const float4*)&hprev[(size_t)nb2 * ldh + tx * 4];
        float4 v3 = *(const float4*)&hprev[(size_t)nb3 * ldh + tx * 4];
        acc.x = fmaxf(acc.x, fmaxf(fmaxf(v0.x, v1.x), fmaxf(v2.x, v3.x)));
        acc.y = fmaxf(acc.y, fmaxf(fmaxf(v0.y, v1.y), fmaxf(v2.y, v3.y)));
        acc.z = fmaxf(acc.z, fmaxf(fmaxf(v0.z, v1.z), fmaxf(v2.z, v3.z)));
        acc.w = fmaxf(acc.w, fmaxf(fmaxf(v0.w, v1.w), fmaxf(v2.w, v3.w)));
    }
    for (; p < p1; ++p) {
        int nb = g_col[p];
        float4 v = *(const float4*)&hprev[(size_t)nb * ldh + tx * 4];
        acc.x = fmaxf(acc.x, v.x); acc.y = fmaxf(acc.y, v.y);
        acc.z = fmaxf(acc.z, v.z); acc.w = fmaxf(acc.w, v.w);
    }
    if (p0 == p1) acc = make_float4(0.f, 0.f, 0.f, 0.f);
    *(float4*)&g_agg[(size_t)node * DEMB + tx * 4] = acc;
}

// ---------------- tf32 tensor-core GEMM, cp.async double-buffered ---------------
// C[M,ldc] = A1@B1 + A2@B2 + bias (optional relu), output tf32-rounded.
// Operands pre-rounded to tf32. 128x128x32 tile, 256 threads (2x4 warps, 64x32).
#define BM 128
#define BN 128
#define BK 32
#define ASTR 36           // A smem [m][k] stride: banks 4g+t4 -> conflict-free
#define BSTR 136          // B smem [k][n] stride: banks 8t4+g -> conflict-free
#define AS_STAGE (BM * ASTR)          // 4608 floats
#define BS_STAGE (BK * BSTR)          // 4352 floats
#define GEMM_SMEM_BYTES ((2 * AS_STAGE + 2 * BS_STAGE) * 4)   // 71680

template <bool RELU>
__global__ __launch_bounds__(256, 2)
void k_gemm_tc(const float* __restrict__ A1, int lda1, const float* __restrict__ B1, int K1,
               const float* __restrict__ A2, int lda2, const float* __restrict__ B2, int K2,
               const float* __restrict__ bias, float* __restrict__ C, int ldc, int M)
{
    extern __shared__ float sm[];
    float* Asm[2] = { sm, sm + AS_STAGE };
    float* Bsm[2] = { sm + 2 * AS_STAGE, sm + 2 * AS_STAGE + BS_STAGE };

    int tid  = threadIdx.x;
    int warp = tid >> 5, lane = tid & 31;
    int wm = warp & 1, wn = warp >> 1;          // 2 x 4 warp grid
    int m_base = wm * 64, n_base = wn * 32;
    int g = lane >> 2, t4 = lane & 3;
    int bm0 = blockIdx.x * BM;
    int bn0 = blockIdx.y * BN;
    int n1 = K1 / BK;
    int nT = n1 + ((A2 != nullptr) ? (K2 / BK) : 0);

    float c[4][4][4];
    #pragma unroll
    for (int i = 0; i < 4; i++)
        #pragma unroll
        for (int j = 0; j < 4; j++)
            #pragma unroll
            for (int q = 0; q < 4; q++) c[i][j][q] = 0.f;

    auto load_tile = [&](int tt, int st) {
        const float *A, *B; int lda, k0;
        if (tt < n1) { A = A1; B = B1; lda = lda1; k0 = tt * BK; }
        else         { A = A2; B = B2; lda = lda2; k0 = (tt - n1) * BK; }
        #pragma unroll
        for (int t = 0; t < 4; t++) {
            int idx = tid + t * 256;            // 1024 16B chunks for A (128x32)
            int row = idx >> 3, c4 = idx & 7;
            const float* src = A + (size_t)(bm0 + row) * lda + k0 + c4 * 4;
            int sz = (bm0 + row < M) ? 16 : 0;
            cp_async16(smem_u32(&Asm[st][row * ASTR + c4 * 4]), src, sz);
        }
        #pragma unroll
        for (int t = 0; t < 4; t++) {
            int idx = tid + t * 256;            // 1024 16B chunks for B (32x128)
            int row = idx >> 5, cc = idx & 31;
            const float* src = B + (size_t)(k0 + row) * DEMB + bn0 + cc * 4;
            cp_async16(smem_u32(&Bsm[st][row * BSTR + cc * 4]), src, 16);
        }
        asm volatile("cp.async.commit_group;\n" ::: "memory");
    };

    load_tile(0, 0);
    for (int tt = 0; tt < nT; tt++) {
        int st = tt & 1;
        if (tt + 1 < nT) {
            load_tile(tt + 1, st ^ 1);
            asm volatile("cp.async.wait_group 1;\n" ::: "memory");
        } else {
            asm volatile("cp.async.wait_group 0;\n" ::: "memory");
        }
        __syncthreads();

        const float* as = Asm[st];
        const float* bs = Bsm[st];
        #pragma unroll
        for (int ks = 0; ks < 4; ks++) {
            int kk = ks * 8;
            unsigned af[4][4], bf[4][2];
            #pragma unroll
            for (int i = 0; i < 4; i++) {
                int r = m_base + i * 16 + g;
                af[i][0] = __float_as_uint(as[r * ASTR + kk + t4]);
                af[i][1] = __float_as_uint(as[(r + 8) * ASTR + kk + t4]);
                af[i][2] = __float_as_uint(as[r * ASTR + kk + t4 + 4]);
                af[i][3] = __float_as_uint(as[(r + 8) * ASTR + kk + t4 + 4]);
            }
            #pragma unroll
            for (int j = 0; j < 4; j++) {
                int nn = n_base + j * 8 + g;
                bf[j][0] = __float_as_uint(bs[(kk + t4) * BSTR + nn]);
                bf[j][1] = __float_as_uint(bs[(kk + t4 + 4) * BSTR + nn]);
            }
            #pragma unroll
            for (int i = 0; i < 4; i++)
                #pragma unroll
                for (int j = 0; j < 4; j++)
                    mma_tf32(c[i][j], af[i][0], af[i][1], af[i][2], af[i][3],
                             bf[j][0], bf[j][1]);
        }
        __syncthreads();
    }

    // epilogue: bias (+relu), tf32-round, store
    #pragma unroll
    for (int i = 0; i < 4; i++) {
        int row0 = bm0 + m_base + i * 16 + g;
        #pragma unroll
        for (int j = 0; j < 4; j++) {
            int col = bn0 + n_base + j * 8 + 2 * t4;
            float bx = bias[col], by = bias[col + 1];
            float v0 = c[i][j][0] + bx, v1 = c[i][j][1] + by;
            float v2 = c[i][j][2] + bx, v3 = c[i][j][3] + by;
            if (RELU) {
                v0 = fmaxf(v0, 0.f); v1 = fmaxf(v1, 0.f);
                v2 = fmaxf(v2, 0.f); v3 = fmaxf(v3, 0.f);
            }
            if (row0 < M)
                *(float2*)&C[(size_t)row0 * ldc + col] =
                    make_float2(to_tf32(v0), to_tf32(v1));
            if (row0 + 8 < M)
                *(float2*)&C[(size_t)(row0 + 8) * ldc + col] =
                    make_float2(to_tf32(v2), to_tf32(v3));
        }
    }
}

// ---------------- graph pooling -------------------------------------------------
__global__ void k_gbounds(const void* batch, int n) {
    int i = blockIdx.x * blockDim.x + threadIdx.x;
    int stride = gridDim.x * blockDim.x;
    for (int j = i; j < n; j += stride) {
        int b = load_idx(batch, j);
        atomicMin(&g_gstart[b], j);
        atomicAdd(&g_gcnt[b], 1);
    }
}

// grid (NGRAPH, 4), blockDim 64: each block covers 256 columns of one graph
__global__ void k_pool() {
    int gph = blockIdx.x;
    int c = blockIdx.y * 256 + threadIdx.x * 4;
    int s = g_gstart[gph], cnt = g_gcnt[gph];
    float4 acc = make_float4(-INFINITY, -INFINITY, -INFINITY, -INFINITY);
    for (int r = 0; r < cnt; ++r) {
        float4 v = *(const float4*)&g_hc[(size_t)(s + r) * DCAT + c];
        acc.x = fmaxf(acc.x, v.x); acc.y = fmaxf(acc.y, v.y);
        acc.z = fmaxf(acc.z, v.z); acc.w = fmaxf(acc.w, v.w);
    }
    if (cnt == 0) acc = make_float4(0.f, 0.f, 0.f, 0.f);
    *(float4*)&g_pool[gph * DCAT + c] = acc;
}

// ---------------- readout: fc1 -> relu -> fc2 -> log_softmax --------------------
__global__ void k_readout(const float* __restrict__ fc1W, const float* __restrict__ fc1b,
                          const float* __restrict__ fc2W, const float* __restrict__ fc2b,
                          float* __restrict__ out, int out_size)
{
    int g = blockIdx.x;
    int c = threadIdx.x;                // 256 threads
    __shared__ float sg[DCAT];
    __shared__ float sll[DEMB];
    __shared__ float slog[DTGT];
    for (int k = c; k < DCAT; k += 256) sg[k] = g_pool[g * DCAT + k];
    __syncthreads();
    float a = fc1b[c];
    #pragma unroll 4
    for (int k = 0; k < DCAT; k++) a = fmaf(sg[k], fc1W[k * DEMB + c], a);
    float ll = fmaxf(a, 0.f);
    sll[c] = ll;
    __syncthreads();
    if (c < DTGT) {
        float o = fc2b[c];
        #pragma unroll 4
        for (int k = 0; k < DEMB; k++) o = fmaf(sll[k], fc2W[k * DTGT + c], o);
        slog[c] = o;
    }
    __syncthreads();
    if (c < DTGT) {
        float m = -INFINITY;
        for (int k = 0; k < DTGT; k++) m = fmaxf(m, slog[k]);
        float se = 0.f;
        for (int k = 0; k < DTGT; k++) se += expf(slog[k] - m);
        float lse = m + logf(se);
        out[g * DTGT + c] = slog[c] - lse;
        if (out_size >= 2 * NGRAPH * DTGT)
            out[NGRAPH * DTGT + g * DTGT + c] = slog[c];
    }
    if (out_size >= 2 * NGRAPH * DTGT + NGRAPH * DEMB)
        out[2 * NGRAPH * DTGT + g * DEMB + c] = ll;
}

__global__ void k_zero(float* p, int n) {
    int i = blockIdx.x * blockDim.x + threadIdx.x;
    int stride = gridDim.x * blockDim.x;
    for (int j = i; j < n; j += stride) p[j] = 0.f;
}

// ---------------- launch --------------------------------------------------------
extern "C" void kernel_launch(void* const* d_in, const int* in_sizes, int n_in,
                              void* d_out, int out_size)
{
    const float* x     = (const float*)d_in[0];
    const void*  ei    = d_in[1];
    const void*  batch = d_in[2];
    const float* W[4][5];
    for (int l = 0; l < 4; l++)
        for (int k = 0; k < 5; k++)
            W[l][k] = (const float*)d_in[3 + 5 * l + k];   // Wl, bl, Wr, Wm, bm
    const float* fc1W = (const float*)d_in[23];
    const float* fc1b = (const float*)d_in[24];
    const float* fc2W = (const float*)d_in[25];
    const float* fc2b = (const float*)d_in[26];
    float* out = (float*)d_out;

    float* hc_base  = nullptr;
    float* agg_base = nullptr;
    float* mid_base = nullptr;
    float* xtf_base = nullptr;
    float* wtf_base = nullptr;
    cudaGetSymbolAddress((void**)&hc_base,  g_hc);
    cudaGetSymbolAddress((void**)&agg_base, g_agg);
    cudaGetSymbolAddress((void**)&mid_base, g_mid);
    cudaGetSymbolAddress((void**)&xtf_base, g_xtf);
    cudaGetSymbolAddress((void**)&wtf_base, g_wtf);

    cudaFuncSetAttribute(k_gemm_tc<false>, cudaFuncAttributeMaxDynamicSharedMemorySize,
                         GEMM_SMEM_BYTES);
    cudaFuncSetAttribute(k_gemm_tc<true>,  cudaFuncAttributeMaxDynamicSharedMemorySize,
                         GEMM_SMEM_BYTES);

    int Nn = in_sizes[0] / DFEAT;
    long long E = in_sizes[1] / 2;
    if (Nn > NNODES) Nn = NNODES;
    if (E > NEDGES) E = NEDGES;

    int tb = 256;
    int gbN = (Nn + tb - 1) / tb;
    int gbE = (int)((E + tb - 1) / tb); if (gbE > 2048) gbE = 2048;
    int nScanBlk = (Nn + 1023) / 1024;

    // weight tf32 table offsets
    int wlen[4][3], woff[4][3];
    int run = 0;
    for (int l = 0; l < 4; l++) {
        int din = (l == 0) ? DFEAT : DEMB;
        wlen[l][0] = din * DEMB;   // Wl
        wlen[l][1] = din * DEMB;   // Wr
        wlen[l][2] = DEMB * DEMB;  // Wm
        for (int k = 0; k < 3; k++) { woff[l][k] = run; run += wlen[l][k]; }
    }
    WArgs wa;
    for (int l = 0; l < 4; l++) {
        wa.s[l * 3 + 0] = { W[l][0], woff[l][0], wlen[l][0] };
        wa.s[l * 3 + 1] = { W[l][2], woff[l][1], wlen[l][1] };
        wa.s[l * 3 + 2] = { W[l][3], woff[l][2], wlen[l][2] };
    }

    k_init<<<gbN, tb>>>(Nn);
    k_detect<<<512, tb>>>(ei, E, Nn);
    k_hist<<<gbE, tb>>>(ei, E);
    k_scan1<<<nScanBlk, 1024>>>(Nn);
    k_scan2<<<1, 32>>>(nScanBlk);
    k_scan3<<<nScanBlk, 1024>>>(Nn);
    k_scatter<<<gbE, tb>>>(ei, E);
    k_zero<<<(out_size + tb - 1) / tb, tb>>>(out, out_size);
    k_cvtX<<<512, tb>>>(x, Nn * DFEAT);
    k_cvtW<<<256, tb>>>(wa);

    dim3 segBlk(64, 4);
    int segGrid = (Nn + 3) / 4;
    dim3 gemmGrid((Nn + BM - 1) / BM, DEMB / BN);

    for (int l = 0; l < 4; l++) {
        const float* hp;
        int ldh, din;
        if (l == 0) { hp = xtf_base;                         ldh = DFEAT; din = DFEAT; }
        else        { hp = hc_base + (size_t)(l - 1) * DEMB; ldh = DCAT;  din = DEMB;  }

        k_segmax<<<segGrid, segBlk>>>(hp, ldh, din, Nn);
        // mid = agg @ Wl + hp @ Wr + bl
        k_gemm_tc<false><<<gemmGrid, 256, GEMM_SMEM_BYTES>>>(
            agg_base, DEMB, wtf_base + woff[l][0], din,
            hp, ldh,        wtf_base + woff[l][1], din,
            W[l][1], mid_base, DEMB, Nn);
        // hc[:, l*256:(l+1)*256] = relu(mid @ Wm + bm)
        k_gemm_tc<true><<<gemmGrid, 256, GEMM_SMEM_BYTES>>>(
            mid_base, DEMB, wtf_base + woff[l][2], DEMB,
            nullptr, 0, nullptr, 0,
            W[l][4], hc_base + (size_t)l * DEMB, DCAT, Nn);
    }

    k_gbounds<<<gbN, tb>>>(batch, Nn);
    dim3 poolGrid(NGRAPH, 4);
    k_pool<<<poolGrid, 64>>>();
    k_readout<<<NGRAPH, 256>>>(fc1W, fc1b, fc2W, fc2b, out, out_size);
}